// round 1
// baseline (speedup 1.0000x reference)
#include <cuda_runtime.h>
#include <cstdint>

#define N_NODES 100000
#define N_EDGES 3200000
#define IN_DIM  500
#define HID     16
#define OUT_DIM 500

// ---------------- scratch (device globals: no cudaMalloc allowed) ----------
__device__ float g_deg [N_NODES];
__device__ float g_dis [N_NODES];
__device__ float g_norm[N_EDGES];
__device__ float g_t   [N_NODES * HID];   // pre-aggregation features
__device__ float g_a   [N_NODES * HID];   // post-aggregation features

// ---------------- degree / normalization -----------------------------------
__global__ void k_init_deg() {
    int i = blockIdx.x * blockDim.x + threadIdx.x;
    if (i < N_NODES) g_deg[i] = 1.0f;            // self-loop contributes 1
}

__global__ void k_deg(const int* __restrict__ dst) {
    int e = blockIdx.x * blockDim.x + threadIdx.x;
    if (e < N_EDGES) atomicAdd(&g_deg[dst[e]], 1.0f);
}

__global__ void k_dis() {
    int i = blockIdx.x * blockDim.x + threadIdx.x;
    if (i < N_NODES) g_dis[i] = rsqrtf(g_deg[i]);
}

__global__ void k_norm(const int* __restrict__ src, const int* __restrict__ dst) {
    int e = blockIdx.x * blockDim.x + threadIdx.x;
    if (e < N_EDGES) g_norm[e] = g_dis[src[e]] * g_dis[dst[e]];
}

// ---------------- zero the aggregation buffer ------------------------------
__global__ void k_zero_a() {
    int i = blockIdx.x * blockDim.x + threadIdx.x;   // quad index
    if (i < N_NODES * 4) ((float4*)g_a)[i] = make_float4(0.f, 0.f, 0.f, 0.f);
}

// ---------------- GEMM1: g_t = X @ W1   [100k,500]x[500,16] ----------------
#define G1_ACC(sv, kk) do { \
    const float4* wr_ = &Ws[(kk) * 4]; \
    float4 w0_ = wr_[0], w1_ = wr_[1], w2_ = wr_[2], w3_ = wr_[3]; \
    a0.x = fmaf(sv, w0_.x, a0.x); a0.y = fmaf(sv, w0_.y, a0.y); \
    a0.z = fmaf(sv, w0_.z, a0.z); a0.w = fmaf(sv, w0_.w, a0.w); \
    a1.x = fmaf(sv, w1_.x, a1.x); a1.y = fmaf(sv, w1_.y, a1.y); \
    a1.z = fmaf(sv, w1_.z, a1.z); a1.w = fmaf(sv, w1_.w, a1.w); \
    a2.x = fmaf(sv, w2_.x, a2.x); a2.y = fmaf(sv, w2_.y, a2.y); \
    a2.z = fmaf(sv, w2_.z, a2.z); a2.w = fmaf(sv, w2_.w, a2.w); \
    a3.x = fmaf(sv, w3_.x, a3.x); a3.y = fmaf(sv, w3_.y, a3.y); \
    a3.z = fmaf(sv, w3_.z, a3.z); a3.w = fmaf(sv, w3_.w, a3.w); \
} while (0)

__global__ void __launch_bounds__(256) k_gemm1(const float* __restrict__ x,
                                               const float* __restrict__ W1) {
    __shared__ float4 Ws[IN_DIM * 4];                // 500 rows x 16 floats = 32 KB
    const float4* Wv = (const float4*)W1;
    for (int i = threadIdx.x; i < IN_DIM * 4; i += 256) Ws[i] = Wv[i];
    __syncthreads();

    int row = blockIdx.x * 256 + threadIdx.x;
    if (row >= N_NODES) return;

    float4 a0 = make_float4(0.f,0.f,0.f,0.f), a1 = a0, a2 = a0, a3 = a0;
    const float4* xr = (const float4*)(x + (long)row * IN_DIM);

    #pragma unroll 5
    for (int k4 = 0; k4 < IN_DIM / 4; k4++) {
        float4 xv = xr[k4];
        int kb = k4 * 4;
        G1_ACC(xv.x, kb + 0);
        G1_ACC(xv.y, kb + 1);
        G1_ACC(xv.z, kb + 2);
        G1_ACC(xv.w, kb + 3);
    }
    float4* tr = (float4*)(g_t + (long)row * HID);
    tr[0] = a0; tr[1] = a1; tr[2] = a2; tr[3] = a3;
}

// ---------------- aggregation: g_a[dst] += norm * g_t[src] -----------------
__global__ void __launch_bounds__(256) k_agg(const int* __restrict__ src,
                                             const int* __restrict__ dst) {
    int e = blockIdx.x * blockDim.x + threadIdx.x;
    int s, d; float w;
    if (e < N_EDGES) {
        s = src[e]; d = dst[e]; w = g_norm[e];
    } else if (e < N_EDGES + N_NODES) {
        int i = e - N_EDGES;
        s = i; d = i;
        float q = g_dis[i];
        w = q * q;
    } else {
        return;
    }
    const float4* hp = (const float4*)(g_t + (long)s * HID);
    float* ap = g_a + (long)d * HID;
    #pragma unroll
    for (int q = 0; q < 4; q++) {
        float4 v = hp[q];
        v.x *= w; v.y *= w; v.z *= w; v.w *= w;
        asm volatile("red.global.add.v4.f32 [%0], {%1, %2, %3, %4};"
                     :: "l"(ap + q * 4), "f"(v.x), "f"(v.y), "f"(v.z), "f"(v.w)
                     : "memory");
    }
}

// ---------------- fused relu(bias) + 16x16 GEMM: g_t = relu(g_a+b1) @ W2 ---
__global__ void __launch_bounds__(256) k_relu_gemm2(const float* __restrict__ b1,
                                                    const float* __restrict__ W2) {
    __shared__ float Ws[HID * HID];
    __shared__ float bs[HID];
    Ws[threadIdx.x] = W2[threadIdx.x];               // blockDim == 256 == HID*HID
    if (threadIdx.x < HID) bs[threadIdx.x] = b1[threadIdx.x];
    __syncthreads();

    int row = blockIdx.x * 256 + threadIdx.x;
    if (row >= N_NODES) return;

    float h[HID];
    const float4* ar = (const float4*)(g_a + (long)row * HID);
    #pragma unroll
    for (int q = 0; q < 4; q++) {
        float4 v = ar[q];
        h[q*4+0] = fmaxf(v.x + bs[q*4+0], 0.f);
        h[q*4+1] = fmaxf(v.y + bs[q*4+1], 0.f);
        h[q*4+2] = fmaxf(v.z + bs[q*4+2], 0.f);
        h[q*4+3] = fmaxf(v.w + bs[q*4+3], 0.f);
    }
    float acc[HID] = {};
    #pragma unroll
    for (int k = 0; k < HID; k++) {
        float s = h[k];
        #pragma unroll
        for (int j = 0; j < HID; j++) acc[j] = fmaf(s, Ws[k*HID+j], acc[j]);
    }
    float4* tr = (float4*)(g_t + (long)row * HID);
    tr[0] = make_float4(acc[0],  acc[1],  acc[2],  acc[3]);
    tr[1] = make_float4(acc[4],  acc[5],  acc[6],  acc[7]);
    tr[2] = make_float4(acc[8],  acc[9],  acc[10], acc[11]);
    tr[3] = make_float4(acc[12], acc[13], acc[14], acc[15]);
}

// ---------------- plain relu(bias): g_t = relu(g_a + b2) -------------------
__global__ void k_relu_bias(const float* __restrict__ b2) {
    int i = blockIdx.x * blockDim.x + threadIdx.x;   // quad index
    if (i >= N_NODES * 4) return;
    float4 v = ((const float4*)g_a)[i];
    int q = (i & 3) * 4;
    v.x = fmaxf(v.x + b2[q+0], 0.f);
    v.y = fmaxf(v.y + b2[q+1], 0.f);
    v.z = fmaxf(v.z + b2[q+2], 0.f);
    v.w = fmaxf(v.w + b2[q+3], 0.f);
    ((float4*)g_t)[i] = v;
}

// ---------------- GEMM3: out = g_a @ W3 + b3  [100k,16]x[16,500] -----------
__global__ void __launch_bounds__(128) k_gemm3(const float* __restrict__ W3,
                                               const float* __restrict__ b3,
                                               float* __restrict__ out) {
    __shared__ float4 as4[64 * 4];                   // 64 rows x 16 floats
    int tid = threadIdx.x;
    int r0  = blockIdx.x * 64;
    int nrows = N_NODES - r0; if (nrows > 64) nrows = 64;

    const float4* av = (const float4*)(g_a + (long)r0 * HID);
    for (int i = tid; i < nrows * 4; i += 128) as4[i] = av[i];
    __syncthreads();

    if (tid >= 125) return;                          // 125 threads cover 500 cols
    int c = tid * 4;

    float4 w[16];
    #pragma unroll
    for (int k = 0; k < HID; k++) w[k] = *(const float4*)(W3 + k * OUT_DIM + c);
    float4 bb = *(const float4*)(b3 + c);

    for (int r = 0; r < nrows; r++) {
        float4 acc = bb;
        #pragma unroll
        for (int k4 = 0; k4 < 4; k4++) {
            float4 a = as4[r * 4 + k4];
            int kb = k4 * 4;
            acc.x = fmaf(a.x, w[kb+0].x, acc.x); acc.y = fmaf(a.x, w[kb+0].y, acc.y);
            acc.z = fmaf(a.x, w[kb+0].z, acc.z); acc.w = fmaf(a.x, w[kb+0].w, acc.w);
            acc.x = fmaf(a.y, w[kb+1].x, acc.x); acc.y = fmaf(a.y, w[kb+1].y, acc.y);
            acc.z = fmaf(a.y, w[kb+1].z, acc.z); acc.w = fmaf(a.y, w[kb+1].w, acc.w);
            acc.x = fmaf(a.z, w[kb+2].x, acc.x); acc.y = fmaf(a.z, w[kb+2].y, acc.y);
            acc.z = fmaf(a.z, w[kb+2].z, acc.z); acc.w = fmaf(a.z, w[kb+2].w, acc.w);
            acc.x = fmaf(a.w, w[kb+3].x, acc.x); acc.y = fmaf(a.w, w[kb+3].y, acc.y);
            acc.z = fmaf(a.w, w[kb+3].z, acc.z); acc.w = fmaf(a.w, w[kb+3].w, acc.w);
        }
        *(float4*)(out + (long)(r0 + r) * OUT_DIM + c) = acc;
    }
}

// ---------------- launch ----------------------------------------------------
extern "C" void kernel_launch(void* const* d_in, const int* in_sizes, int n_in,
                              void* d_out, int out_size) {
    const float* x   = (const float*)d_in[0];
    const int*   ei  = (const int*)  d_in[1];
    const float* W1  = (const float*)d_in[2];
    const float* b1  = (const float*)d_in[3];
    const float* W2  = (const float*)d_in[4];
    const float* b2  = (const float*)d_in[5];
    const float* W3  = (const float*)d_in[6];
    const float* b3  = (const float*)d_in[7];
    float* out = (float*)d_out;

    const int* src = ei;            // edge_index[0]
    const int* dst = ei + N_EDGES;  // edge_index[1]

    const int TB = 256;
    const int gN  = (N_NODES + TB - 1) / TB;               // 391
    const int gE  = (N_EDGES + TB - 1) / TB;               // 12500
    const int gEN = (N_EDGES + N_NODES + TB - 1) / TB;     // 12891
    const int gQ  = (N_NODES * 4 + TB - 1) / TB;           // 1563
    const int g64 = (N_NODES + 63) / 64;                   // 1563

    // normalization
    k_init_deg<<<gN, TB>>>();
    k_deg<<<gE, TB>>>(dst);
    k_dis<<<gN, TB>>>();
    k_norm<<<gE, TB>>>(src, dst);

    // layer 1
    k_gemm1<<<gN, TB>>>(x, W1);
    k_zero_a<<<gQ, TB>>>();
    k_agg<<<gEN, TB>>>(src, dst);

    // layer 2 (fused relu+bias1 + 16x16 GEMM)
    k_relu_gemm2<<<gN, TB>>>(b1, W2);
    k_zero_a<<<gQ, TB>>>();
    k_agg<<<gEN, TB>>>(src, dst);

    // layer 3: aggregate first (commutes with linear map), then GEMM up
    k_relu_bias<<<gQ, TB>>>(b2);
    k_zero_a<<<gQ, TB>>>();
    k_agg<<<gEN, TB>>>(src, dst);
    k_gemm3<<<g64, 128>>>(W3, b3, out);
}

// round 2
// speedup vs baseline: 1.0548x; 1.0548x over previous
#include <cuda_runtime.h>
#include <cstdint>

#define N_NODES 100000
#define N_EDGES 3200000
#define IN_DIM  500
#define HID     16
#define OUT_DIM 500

// ---------------- scratch (device globals: no cudaMalloc allowed) ----------
__device__ float g_deg [N_NODES];
__device__ float g_dis [N_NODES];
__device__ float g_t   [N_NODES * HID];   // pre-scaled pre-aggregation features
__device__ float g_a   [N_NODES * HID];   // aggregation accumulator (zeroed by consumers)

// ---------------- f32x2 packed helpers --------------------------------------
__device__ __forceinline__ void fma2(unsigned long long& d,
                                     unsigned long long a, unsigned long long b) {
    asm("fma.rn.f32x2 %0, %1, %2, %0;" : "+l"(d) : "l"(a), "l"(b));
}
__device__ __forceinline__ void mul2(unsigned long long& d, unsigned long long s) {
    asm("mul.rn.f32x2 %0, %0, %1;" : "+l"(d) : "l"(s));
}
__device__ __forceinline__ unsigned long long pack2(float f) {
    unsigned long long r; unsigned u = __float_as_uint(f);
    asm("mov.b64 %0, {%1, %1};" : "=l"(r) : "r"(u));
    return r;
}
__device__ __forceinline__ unsigned long long pack2(float lo, float hi) {
    unsigned long long r;
    asm("mov.b64 %0, {%1, %2};" : "=l"(r) : "r"(__float_as_uint(lo)), "r"(__float_as_uint(hi)));
    return r;
}
__device__ __forceinline__ float2 unpack2(unsigned long long v) {
    unsigned a, b;
    asm("mov.b64 {%0, %1}, %2;" : "=r"(a), "=r"(b) : "l"(v));
    return make_float2(__uint_as_float(a), __uint_as_float(b));
}

// ---------------- degree / normalization -----------------------------------
__global__ void k_init_deg() {
    int i = blockIdx.x * blockDim.x + threadIdx.x;
    if (i < N_NODES) g_deg[i] = 1.0f;            // self-loop contributes 1
}

__global__ void k_deg(const int* __restrict__ dst) {
    int e = blockIdx.x * blockDim.x + threadIdx.x;
    if (e < N_EDGES) atomicAdd(&g_deg[dst[e]], 1.0f);
}

__global__ void k_dis() {
    int i = blockIdx.x * blockDim.x + threadIdx.x;
    if (i < N_NODES) g_dis[i] = rsqrtf(g_deg[i]);
}

// ---------------- GEMM1: g_t = dis[row] * (X @ W1)   [100k,500]x[500,16] ----
#define G1K(xp, kk) do { \
    const ulonglong2* wr_ = &Ws[(kk) * 4]; \
    ulonglong2 w0_ = wr_[0], w1_ = wr_[1], w2_ = wr_[2], w3_ = wr_[3]; \
    fma2(a0, xp, w0_.x); fma2(a1, xp, w0_.y); \
    fma2(a2, xp, w1_.x); fma2(a3, xp, w1_.y); \
    fma2(a4, xp, w2_.x); fma2(a5, xp, w2_.y); \
    fma2(a6, xp, w3_.x); fma2(a7, xp, w3_.y); \
} while (0)

__global__ void __launch_bounds__(256) k_gemm1(const float* __restrict__ x,
                                               const float* __restrict__ W1) {
    __shared__ ulonglong2 Ws[IN_DIM * 4];        // 500 rows x 16 floats = 32 KB
    const ulonglong2* Wv = (const ulonglong2*)W1;
    for (int i = threadIdx.x; i < IN_DIM * 4; i += 256) Ws[i] = Wv[i];
    __syncthreads();

    int row = blockIdx.x * 256 + threadIdx.x;
    if (row >= N_NODES) return;

    unsigned long long a0 = 0, a1 = 0, a2 = 0, a3 = 0, a4 = 0, a5 = 0, a6 = 0, a7 = 0;
    const float4* xr = (const float4*)(x + (long)row * IN_DIM);

    #pragma unroll 5
    for (int k4 = 0; k4 < IN_DIM / 4; k4++) {
        float4 xv = xr[k4];
        int kb = k4 * 4;
        { unsigned long long xp = pack2(xv.x); G1K(xp, kb + 0); }
        { unsigned long long xp = pack2(xv.y); G1K(xp, kb + 1); }
        { unsigned long long xp = pack2(xv.z); G1K(xp, kb + 2); }
        { unsigned long long xp = pack2(xv.w); G1K(xp, kb + 3); }
    }

    unsigned long long sp = pack2(g_dis[row]);   // pre-scale by dis[row]
    mul2(a0, sp); mul2(a1, sp); mul2(a2, sp); mul2(a3, sp);
    mul2(a4, sp); mul2(a5, sp); mul2(a6, sp); mul2(a7, sp);

    ulonglong2* tr = (ulonglong2*)(g_t + (long)row * HID);
    tr[0] = make_ulonglong2(a0, a1);
    tr[1] = make_ulonglong2(a2, a3);
    tr[2] = make_ulonglong2(a4, a5);
    tr[3] = make_ulonglong2(a6, a7);
}

// ---------------- aggregation: g_a[dst] += g_t[src] (unweighted) ------------
__global__ void __launch_bounds__(256) k_agg(const int* __restrict__ src,
                                             const int* __restrict__ dst) {
    int e = blockIdx.x * blockDim.x + threadIdx.x;
    if (e >= N_EDGES) return;
    int s = __ldg(src + e), d = __ldg(dst + e);
    const float4* hp = (const float4*)(g_t + (long)s * HID);
    float* ap = g_a + (long)d * HID;
    #pragma unroll
    for (int q = 0; q < 4; q++) {
        float4 v = __ldg(hp + q);
        asm volatile("red.global.add.v4.f32 [%0], {%1, %2, %3, %4};"
                     :: "l"(ap + q * 4), "f"(v.x), "f"(v.y), "f"(v.z), "f"(v.w)
                     : "memory");
    }
}

// ---- consumer+producer: h1 = relu(dis*(g_a+g_t)+b1); g_t = dis*(h1@W2); g_a=0
__global__ void __launch_bounds__(256) k_relu_gemm2(const float* __restrict__ b1,
                                                    const float* __restrict__ W2) {
    __shared__ float Ws[HID * HID];
    __shared__ float bs[HID];
    Ws[threadIdx.x] = W2[threadIdx.x];           // blockDim == 256 == HID*HID
    if (threadIdx.x < HID) bs[threadIdx.x] = b1[threadIdx.x];
    __syncthreads();

    int row = blockIdx.x * 256 + threadIdx.x;
    if (row >= N_NODES) return;
    float s = g_dis[row];

    float4* ar = (float4*)(g_a + (long)row * HID);
    float4* tr = (float4*)(g_t + (long)row * HID);
    float h[HID];
    const float4 z4 = make_float4(0.f, 0.f, 0.f, 0.f);
    #pragma unroll
    for (int q = 0; q < 4; q++) {
        float4 va = ar[q], vt = tr[q];
        h[q*4+0] = fmaxf(fmaf(s, va.x + vt.x, bs[q*4+0]), 0.f);
        h[q*4+1] = fmaxf(fmaf(s, va.y + vt.y, bs[q*4+1]), 0.f);
        h[q*4+2] = fmaxf(fmaf(s, va.z + vt.z, bs[q*4+2]), 0.f);
        h[q*4+3] = fmaxf(fmaf(s, va.w + vt.w, bs[q*4+3]), 0.f);
        ar[q] = z4;                              // fused re-zero of g_a
    }
    float acc[HID] = {};
    #pragma unroll
    for (int k = 0; k < HID; k++) {
        float v = h[k];
        #pragma unroll
        for (int j = 0; j < HID; j++) acc[j] = fmaf(v, Ws[k*HID+j], acc[j]);
    }
    // write pre-scaled ht2 = dis[row] * (h1 @ W2)
    tr[0] = make_float4(acc[0]*s,  acc[1]*s,  acc[2]*s,  acc[3]*s);
    tr[1] = make_float4(acc[4]*s,  acc[5]*s,  acc[6]*s,  acc[7]*s);
    tr[2] = make_float4(acc[8]*s,  acc[9]*s,  acc[10]*s, acc[11]*s);
    tr[3] = make_float4(acc[12]*s, acc[13]*s, acc[14]*s, acc[15]*s);
}

// ---- consumer: h2 = relu(dis*(g_a+g_t)+b2); g_t = dis*h2; g_a=0 ------------
__global__ void __launch_bounds__(256) k_relu_bias(const float* __restrict__ b2) {
    int row = blockIdx.x * blockDim.x + threadIdx.x;
    if (row >= N_NODES) return;
    float s = g_dis[row];
    float4* ar = (float4*)(g_a + (long)row * HID);
    float4* tr = (float4*)(g_t + (long)row * HID);
    const float4 z4 = make_float4(0.f, 0.f, 0.f, 0.f);
    #pragma unroll
    for (int q = 0; q < 4; q++) {
        float4 va = ar[q], vt = tr[q];
        float4 r;
        r.x = s * fmaxf(fmaf(s, va.x + vt.x, b2[q*4+0]), 0.f);
        r.y = s * fmaxf(fmaf(s, va.y + vt.y, b2[q*4+1]), 0.f);
        r.z = s * fmaxf(fmaf(s, va.z + vt.z, b2[q*4+2]), 0.f);
        r.w = s * fmaxf(fmaf(s, va.w + vt.w, b2[q*4+3]), 0.f);
        tr[q] = r;
        ar[q] = z4;                              // fused re-zero of g_a
    }
}

// ---- GEMM3: A = dis*(g_a+g_t); out = A@W3 + b3; g_a=0  [100k,16]x[16,500] --
__global__ void __launch_bounds__(128) k_gemm3(const float* __restrict__ W3,
                                               const float* __restrict__ b3,
                                               float* __restrict__ out) {
    __shared__ float4 as4[64 * 4];               // 64 rows x 16 floats
    int tid = threadIdx.x;
    int r0  = blockIdx.x * 64;
    int nrows = N_NODES - r0; if (nrows > 64) nrows = 64;

    const float4 z4 = make_float4(0.f, 0.f, 0.f, 0.f);
    for (int i = tid; i < nrows * 4; i += 128) {
        int r = i >> 2, q = i & 3;
        int row = r0 + r;
        float s = g_dis[row];
        float4* ap = (float4*)(g_a + (long)row * HID);
        float4 va = ap[q];
        float4 vt = ((const float4*)(g_t + (long)row * HID))[q];
        as4[i] = make_float4(s*(va.x+vt.x), s*(va.y+vt.y), s*(va.z+vt.z), s*(va.w+vt.w));
        ap[q] = z4;                              // fused re-zero of g_a
    }
    __syncthreads();

    if (tid >= 125) return;                      // 125 threads cover 500 cols
    int c = tid * 4;

    unsigned long long w[32];                    // 16 k-rows x 2 packed pairs
    #pragma unroll
    for (int k = 0; k < HID; k++) {
        float4 wv = *(const float4*)(W3 + k * OUT_DIM + c);
        w[k*2+0] = pack2(wv.x, wv.y);
        w[k*2+1] = pack2(wv.z, wv.w);
    }
    float4 bb = *(const float4*)(b3 + c);
    unsigned long long b01 = pack2(bb.x, bb.y), b23 = pack2(bb.z, bb.w);

    for (int r = 0; r < nrows; r++) {
        unsigned long long acc0 = b01, acc1 = b23;
        #pragma unroll
        for (int k4 = 0; k4 < 4; k4++) {
            float4 a = as4[r * 4 + k4];
            int kb = k4 * 4;
            { unsigned long long ap = pack2(a.x); fma2(acc0, ap, w[(kb+0)*2]); fma2(acc1, ap, w[(kb+0)*2+1]); }
            { unsigned long long ap = pack2(a.y); fma2(acc0, ap, w[(kb+1)*2]); fma2(acc1, ap, w[(kb+1)*2+1]); }
            { unsigned long long ap = pack2(a.z); fma2(acc0, ap, w[(kb+2)*2]); fma2(acc1, ap, w[(kb+2)*2+1]); }
            { unsigned long long ap = pack2(a.w); fma2(acc0, ap, w[(kb+3)*2]); fma2(acc1, ap, w[(kb+3)*2+1]); }
        }
        float2 lo = unpack2(acc0), hi = unpack2(acc1);
        *(float4*)(out + (long)(r0 + r) * OUT_DIM + c) = make_float4(lo.x, lo.y, hi.x, hi.y);
    }
}

// ---------------- launch ----------------------------------------------------
extern "C" void kernel_launch(void* const* d_in, const int* in_sizes, int n_in,
                              void* d_out, int out_size) {
    const float* x   = (const float*)d_in[0];
    const int*   ei  = (const int*)  d_in[1];
    const float* W1  = (const float*)d_in[2];
    const float* b1  = (const float*)d_in[3];
    const float* W2  = (const float*)d_in[4];
    const float* b2  = (const float*)d_in[5];
    const float* W3  = (const float*)d_in[6];
    const float* b3  = (const float*)d_in[7];
    float* out = (float*)d_out;

    const int* src = ei;            // edge_index[0]
    const int* dst = ei + N_EDGES;  // edge_index[1]

    const int TB = 256;
    const int gN  = (N_NODES + TB - 1) / TB;               // 391
    const int gE  = (N_EDGES + TB - 1) / TB;               // 12500
    const int g64 = (N_NODES + 63) / 64;                   // 1563

    // normalization
    k_init_deg<<<gN, TB>>>();
    k_deg<<<gE, TB>>>(dst);
    k_dis<<<gN, TB>>>();

    // layer 1 (g_t pre-scaled by dis)
    k_gemm1<<<gN, TB>>>(x, W1);
    k_agg<<<gE, TB>>>(src, dst);

    // layer 2 (consume agg1, produce pre-scaled ht2, re-zero g_a)
    k_relu_gemm2<<<gN, TB>>>(b1, W2);
    k_agg<<<gE, TB>>>(src, dst);

    // layer 3: finish layer-2 relu, pre-scale h2 by dis, aggregate, then GEMM up
    k_relu_bias<<<gN, TB>>>(b2);
    k_agg<<<gE, TB>>>(src, dst);
    k_gemm3<<<g64, 128>>>(W3, b3, out);
}